// round 13
// baseline (speedup 1.0000x reference)
#include <cuda_runtime.h>
#include <math.h>
#include <stdint.h>

#define NN 500000
#define FF 128
#define HH 64
#define BB 1024
#define TILE 128
#define XS_STRIDE 132
#define WB_STRIDE 68   // u32 stride for packed bf16 W tiles (conflict-free frag loads)

// ---------------- scratch (no allocations allowed) ----------------
__device__ int2   g_spair[2][NN];     // (node idx, segment) in segment-sorted order
__device__ int    g_count[2][BB];
__device__ int    g_cursor[2][BB];
__device__ float  g_acc[2][BB * FF];  // unnormalized e*x sums
__device__ float  g_s[2][BB];         // unnormalized e sums
// pre-split W1^T packed bf16x2: [n 0..63][kp 0..63], kp = k/2 (k even in low half)
__device__ uint32_t g_wb_hi[HH * 64];
__device__ uint32_t g_wb_lo[HH * 64];

// ---------------- helpers ----------------
__device__ __forceinline__ uint32_t bf16x2_pack(float up, float lo) {
    uint32_t d;
    asm("cvt.rn.bf16x2.f32 %0, %1, %2;" : "=r"(d) : "f"(up), "f"(lo));
    return d;
}
__device__ __forceinline__ float bf16_lo_as_f32(uint32_t u) { return __uint_as_float(u << 16); }
__device__ __forceinline__ float bf16_hi_as_f32(uint32_t u) { return __uint_as_float(u & 0xFFFF0000u); }

__device__ __forceinline__ float tanh_fast(float v) {
    float e = __expf(2.0f * v);
    return 1.0f - __fdividef(2.0f, e + 1.0f);
}
__device__ __forceinline__ void mma_bf16(float* c, const uint32_t* a, const uint32_t* b) {
    asm volatile(
        "mma.sync.aligned.m16n8k16.row.col.f32.bf16.bf16.f32 "
        "{%0,%1,%2,%3}, {%4,%5,%6,%7}, {%8,%9}, {%0,%1,%2,%3};"
        : "+f"(c[0]), "+f"(c[1]), "+f"(c[2]), "+f"(c[3])
        : "r"(a[0]), "r"(a[1]), "r"(a[2]), "r"(a[3]), "r"(b[0]), "r"(b[1]));
}
__device__ __forceinline__ void split2(float2 q, uint32_t& hi, uint32_t& lo) {
    hi = bf16x2_pack(q.y, q.x);
    float hx = bf16_lo_as_f32(hi);
    float hy = bf16_hi_as_f32(hi);
    lo = bf16x2_pack(q.y - hy, q.x - hx);
}

// ---------------- K0: init (zero accumulators + counters) ----------------
__global__ void init_kernel() {
    int i = blockIdx.x * blockDim.x + threadIdx.x;
    if (i < 2 * BB * FF) (&g_acc[0][0])[i] = 0.0f;
    if (i < 2 * BB) {
        (&g_s[0][0])[i] = 0.0f;
        (&g_count[0][0])[i] = 0;
    }
}

// ---------------- K0b: pre-split + pre-pack W1 ----------------
__global__ void prep_w_kernel(const float* __restrict__ W1) {
    int i = blockIdx.x * blockDim.x + threadIdx.x;
    if (i >= HH * 64) return;
    int n  = i >> 6;
    int kp = i & 63;
    float w0 = W1[(2 * kp)     * HH + n];
    float w1 = W1[(2 * kp + 1) * HH + n];
    uint32_t hi = bf16x2_pack(w1, w0);
    float h0 = bf16_lo_as_f32(hi);
    float h1 = bf16_hi_as_f32(hi);
    uint32_t lo = bf16x2_pack(w1 - h1, w0 - h0);
    g_wb_hi[i] = hi;
    g_wb_lo[i] = lo;
}

// ---------------- K1: histogram of batch ids ----------------
__global__ __launch_bounds__(512) void hist_kernel(
    const int* __restrict__ bA, const int* __restrict__ bB)
{
    int t = blockIdx.y;
    int i0 = (blockIdx.x * 512 + threadIdx.x) * 4;
    if (i0 >= NN) return;   // NN % 4 == 0
    const int* batch = t ? bB : bA;
    int4 bv = *(const int4*)&batch[i0];
    atomicAdd(&g_count[t][bv.x], 1);
    atomicAdd(&g_count[t][bv.y], 1);
    atomicAdd(&g_count[t][bv.z], 1);
    atomicAdd(&g_count[t][bv.w], 1);
}

// ---------------- K2: exclusive prefix scan over segments ----------------
__global__ void scan_kernel() {
    __shared__ int ss[BB];
    int tid = threadIdx.x;
    for (int t = 0; t < 2; ++t) {
        int v = g_count[t][tid];
        ss[tid] = v;
        __syncthreads();
        for (int d = 1; d < BB; d <<= 1) {
            int add = (tid >= d) ? ss[tid - d] : 0;
            __syncthreads();
            ss[tid] += add;
            __syncthreads();
        }
        g_cursor[t][tid] = ss[tid] - v;
        __syncthreads();
    }
}

// ---------------- K3: scatter (node, seg) into segment-sorted order ----------------
__global__ __launch_bounds__(512) void scatter_kernel(
    const int* __restrict__ bA, const int* __restrict__ bB)
{
    int t = blockIdx.y;
    int i0 = (blockIdx.x * 512 + threadIdx.x) * 4;
    if (i0 >= NN) return;   // NN % 4 == 0
    const int* batch = t ? bB : bA;
    int4 bv = *(const int4*)&batch[i0];
    int p0 = atomicAdd(&g_cursor[t][bv.x], 1);
    int p1 = atomicAdd(&g_cursor[t][bv.y], 1);
    int p2 = atomicAdd(&g_cursor[t][bv.z], 1);
    int p3 = atomicAdd(&g_cursor[t][bv.w], 1);
    g_spair[t][p0] = make_int2(i0 + 0, bv.x);
    g_spair[t][p1] = make_int2(i0 + 1, bv.y);
    g_spair[t][p2] = make_int2(i0 + 2, bv.z);
    g_spair[t][p3] = make_int2(i0 + 3, bv.w);
}

// ---------------- K4: fused score + pool (256 thr; warp-parallel pooling sweep) ----------------
// smem words: xs[128][132] + swh/swl + b1s/w2s + es[128] + suacc[8][132] + ses[8] + ssid/sseg[128 ea]
#define SMEM_WORDS (TILE * XS_STRIDE + 2 * (HH * WB_STRIDE) + 64 + 64 + TILE + 8 * 132 + 8 + TILE + TILE)

__global__ __launch_bounds__(256) void score_pool_kernel(
    const float* __restrict__ x1, const float* __restrict__ x2,
    const float* __restrict__ b1v, const float* __restrict__ W2)
{
    extern __shared__ float sm[];
    float*    xs    = sm;
    uint32_t* swh   = (uint32_t*)(xs + TILE * XS_STRIDE);
    uint32_t* swl   = swh + HH * WB_STRIDE;
    float*    b1s   = (float*)(swl + HH * WB_STRIDE);
    float*    w2s   = b1s + 64;
    float*    es    = w2s + 64;
    float*    suacc = es + TILE;          // [8][132]
    float*    ses   = suacc + 8 * 132;    // [8]
    int*      ssid  = (int*)(ses + 8);    // [128]
    int*      sseg  = ssid + TILE;        // [128]

    const int tid  = threadIdx.x;
    const int wid  = tid >> 5;      // 0..7, each warp owns 16 rows
    const int lane = tid & 31;
    const int g    = lane >> 2;
    const int tq   = lane & 3;
    const int t    = blockIdx.y;
    const float* x = t ? x2 : x1;
    const int n0   = blockIdx.x * TILE;

    // load sorted (node, seg) for this tile; pad rows clamp idx (e forced 0 later)
    if (tid < TILE) {
        int pos = n0 + tid;
        int2 pr = g_spair[t][pos < NN ? pos : (NN - 1)];
        ssid[tid] = pr.x;
        sseg[tid] = pr.y;
    }

    // stage packed W (hi+lo): 4096 u32 each
    #pragma unroll
    for (int m = 0; m < 16; ++m) {
        int j = tid + 256 * m;
        int n  = j >> 6;
        int kp = j & 63;
        swh[n * WB_STRIDE + kp] = g_wb_hi[j];
        swl[n * WB_STRIDE + kp] = g_wb_lo[j];
    }
    if (tid < HH) { b1s[tid] = b1v[tid]; w2s[tid] = W2[tid]; }
    __syncthreads();

    // stage x tile: gather sorted rows (512B coalesced float4 per row)
    #pragma unroll
    for (int m = 0; m < 16; ++m) {
        int idx = m * 256 + tid;
        int r = idx >> 5;
        int q = idx & 31;
        float4 v = ((const float4*)x)[(long)ssid[r] * 32 + q];
        *(float4*)&xs[r * XS_STRIDE + q * 4] = v;
    }
    __syncthreads();

    // GEMM: warp computes rows [wid*16, wid*16+16) x 64 hidden (bf16x3 compensated)
    const int base = wid * 16;
    float acc[8][4];
    #pragma unroll
    for (int n = 0; n < 8; ++n)
        #pragma unroll
        for (int c = 0; c < 4; ++c) acc[n][c] = 0.0f;

    #pragma unroll
    for (int kt = 0; kt < 8; ++kt) {
        const int k0  = kt * 16;
        const int kp0 = kt * 8;

        uint32_t bh[8][2], bl[8][2];
        #pragma unroll
        for (int n = 0; n < 8; ++n) {
            int row = (n * 8 + g) * WB_STRIDE + kp0 + tq;
            bh[n][0] = swh[row];
            bh[n][1] = swh[row + 4];
            bl[n][0] = swl[row];
            bl[n][1] = swl[row + 4];
        }

        const int r = base + g;
        float2 q0 = *(const float2*)&xs[r       * XS_STRIDE + k0 + 2 * tq];
        float2 q1 = *(const float2*)&xs[(r + 8) * XS_STRIDE + k0 + 2 * tq];
        float2 q2 = *(const float2*)&xs[r       * XS_STRIDE + k0 + 2 * tq + 8];
        float2 q3 = *(const float2*)&xs[(r + 8) * XS_STRIDE + k0 + 2 * tq + 8];

        uint32_t ahi[4], alo[4];
        split2(q0, ahi[0], alo[0]);
        split2(q1, ahi[1], alo[1]);
        split2(q2, ahi[2], alo[2]);
        split2(q3, ahi[3], alo[3]);

        #pragma unroll
        for (int n = 0; n < 8; ++n) {
            mma_bf16(acc[n], ahi, bh[n]);
            mma_bf16(acc[n], ahi, bl[n]);
            mma_bf16(acc[n], alo, bh[n]);
        }
    }

    // epilogue: tanh + W2 dot -> e into smem (pad rows get e = 0)
    #pragma unroll
    for (int half = 0; half < 2; ++half) {
        float s = 0.0f;
        #pragma unroll
        for (int n = 0; n < 8; ++n) {
            #pragma unroll
            for (int c = 0; c < 2; ++c) {
                int col = n * 8 + 2 * tq + c;
                float h = acc[n][half * 2 + c] + b1s[col];
                s = fmaf(tanh_fast(h), w2s[col], s);
            }
        }
        s += __shfl_xor_sync(0xffffffffu, s, 1);
        s += __shfl_xor_sync(0xffffffffu, s, 2);
        if (tq == 0) {
            int r = base + half * 8 + g;
            es[r] = (n0 + r < NN) ? __expf(s) : 0.0f;
        }
    }
    __syncwarp();

    // warp-parallel pooling sweep over this warp's own 16 sorted rows
    const bool uniform = (sseg[0] == sseg[TILE - 1]);
    {
        float4 pacc = make_float4(0.f, 0.f, 0.f, 0.f);
        float  eac  = 0.0f;
        int    cur  = sseg[base];
        #pragma unroll
        for (int i = 0; i < 16; ++i) {
            int row = base + i;
            int b = sseg[row];
            if (!uniform && b != cur) {              // warp-uniform branch
                atomicAdd(&g_acc[t][cur * FF + 4 * lane + 0], pacc.x);
                atomicAdd(&g_acc[t][cur * FF + 4 * lane + 1], pacc.y);
                atomicAdd(&g_acc[t][cur * FF + 4 * lane + 2], pacc.z);
                atomicAdd(&g_acc[t][cur * FF + 4 * lane + 3], pacc.w);
                if (lane == 0) atomicAdd(&g_s[t][cur], eac);
                pacc = make_float4(0.f, 0.f, 0.f, 0.f);
                eac = 0.0f;
                cur = b;
            }
            float e = es[row];
            float4 xv = *(const float4*)&xs[row * XS_STRIDE + 4 * lane];
            pacc.x = fmaf(e, xv.x, pacc.x);
            pacc.y = fmaf(e, xv.y, pacc.y);
            pacc.z = fmaf(e, xv.z, pacc.z);
            pacc.w = fmaf(e, xv.w, pacc.w);
            eac += e;
        }
        if (uniform) {
            *(float4*)&suacc[wid * 132 + 4 * lane] = pacc;
            if (lane == 0) ses[wid] = eac;
        } else {
            atomicAdd(&g_acc[t][cur * FF + 4 * lane + 0], pacc.x);
            atomicAdd(&g_acc[t][cur * FF + 4 * lane + 1], pacc.y);
            atomicAdd(&g_acc[t][cur * FF + 4 * lane + 2], pacc.z);
            atomicAdd(&g_acc[t][cur * FF + 4 * lane + 3], pacc.w);
            if (lane == 0) atomicAdd(&g_s[t][cur], eac);
        }
    }

    if (uniform) {
        __syncthreads();
        if (tid < FF) {
            int seg = sseg[0];
            float tot = 0.0f;
            #pragma unroll
            for (int w = 0; w < 8; ++w) tot += suacc[w * 132 + tid];
            atomicAdd(&g_acc[t][seg * FF + tid], tot);
            if (tid == 0) {
                float s = 0.0f;
                #pragma unroll
                for (int w = 0; w < 8; ++w) s += ses[w];
                atomicAdd(&g_s[t][seg], s);
            }
        }
    }
}

// ---------------- K5: finalize ----------------
__global__ void finalize_kernel(float* __restrict__ out) {
    int i = blockIdx.x * blockDim.x + threadIdx.x;
    if (i >= BB * FF) return;
    int b = i >> 7;
    float s0 = g_s[0][b], s1 = g_s[1][b];
    float r0 = (s0 > 0.0f) ? g_acc[0][i] / s0 : 0.0f;
    float r1 = (s1 > 0.0f) ? g_acc[1][i] / s1 : 0.0f;
    out[i] = 0.5f * (r0 + r1);
}

// ---------------- launch ----------------
extern "C" void kernel_launch(void* const* d_in, const int* in_sizes, int n_in,
                              void* d_out, int out_size) {
    const float *x1 = 0, *x2 = 0, *W1 = 0, *b1v = 0, *W2 = 0;
    const int *bt1 = 0, *bt2 = 0;
    for (int k = 0; k < n_in; ++k) {
        long s = in_sizes[k];
        if (s == (long)NN * FF) { if (!x1) x1 = (const float*)d_in[k]; else if (!x2) x2 = (const float*)d_in[k]; }
        else if (s == NN)       { if (!bt1) bt1 = (const int*)d_in[k]; else if (!bt2) bt2 = (const int*)d_in[k]; }
        else if (s == FF * HH)  { W1 = (const float*)d_in[k]; }
        else if (s == HH)       { if (!b1v) b1v = (const float*)d_in[k]; else if (!W2) W2 = (const float*)d_in[k]; }
    }
    float* out = (float*)d_out;

    init_kernel<<<(2 * BB * FF + 1023) / 1024, 1024>>>();
    prep_w_kernel<<<(HH * 64 + 255) / 256, 256>>>(W1);

    dim3 gh((NN / 4 + 511) / 512, 2);
    hist_kernel<<<gh, 512>>>(bt1, bt2);

    scan_kernel<<<1, BB>>>();

    scatter_kernel<<<gh, 512>>>(bt1, bt2);

    const int smem_bytes = SMEM_WORDS * (int)sizeof(float);
    cudaFuncSetAttribute(score_pool_kernel, cudaFuncAttributeMaxDynamicSharedMemorySize, smem_bytes);
    dim3 g1((NN + TILE - 1) / TILE, 2);
    score_pool_kernel<<<g1, 256, smem_bytes>>>(x1, x2, b1v, W2);

    finalize_kernel<<<(BB * FF + 255) / 256, 256>>>(out);
}

// round 14
// speedup vs baseline: 1.4380x; 1.4380x over previous
#include <cuda_runtime.h>
#include <math.h>
#include <stdint.h>

#define NN 500000
#define FF 128
#define HH 64
#define BB 1024
#define TILE 128
#define XS_STRIDE 132
#define WB_STRIDE 68   // u32 stride for packed bf16 W tiles (conflict-free frag loads)

// ---------------- scratch (no allocations allowed) ----------------
__device__ float  g_e[2][NN];
__device__ float2 g_pair[2][NN];      // (idx-as-float-bits, e) in segment-sorted order
__device__ int    g_count[2][BB];
__device__ int    g_offset[2][BB + 1];
__device__ int    g_cursor[2][BB];
// pre-split W1^T packed bf16x2: [n 0..63][kp 0..63], kp = k/2 (k even in low half)
__device__ uint32_t g_wb_hi[HH * 64];
__device__ uint32_t g_wb_lo[HH * 64];

// ---------------- helpers ----------------
__device__ __forceinline__ uint32_t bf16x2_pack(float up, float lo) {
    uint32_t d;
    asm("cvt.rn.bf16x2.f32 %0, %1, %2;" : "=r"(d) : "f"(up), "f"(lo));
    return d;
}
__device__ __forceinline__ float bf16_lo_as_f32(uint32_t u) { return __uint_as_float(u << 16); }
__device__ __forceinline__ float bf16_hi_as_f32(uint32_t u) { return __uint_as_float(u & 0xFFFF0000u); }

__device__ __forceinline__ float tanh_fast(float v) {
    float e = __expf(2.0f * v);
    return 1.0f - __fdividef(2.0f, e + 1.0f);
}
__device__ __forceinline__ void mma_bf16(float* c, const uint32_t* a, const uint32_t* b) {
    asm volatile(
        "mma.sync.aligned.m16n8k16.row.col.f32.bf16.bf16.f32 "
        "{%0,%1,%2,%3}, {%4,%5,%6,%7}, {%8,%9}, {%0,%1,%2,%3};"
        : "+f"(c[0]), "+f"(c[1]), "+f"(c[2]), "+f"(c[3])
        : "r"(a[0]), "r"(a[1]), "r"(a[2]), "r"(a[3]), "r"(b[0]), "r"(b[1]));
}
__device__ __forceinline__ void split2(float2 q, uint32_t& hi, uint32_t& lo) {
    hi = bf16x2_pack(q.y, q.x);
    float hx = bf16_lo_as_f32(hi);
    float hy = bf16_hi_as_f32(hi);
    lo = bf16x2_pack(q.y - hy, q.x - hx);
}

// ---------------- K0: init ----------------
__global__ void init_kernel(float* __restrict__ out) {
    int i = blockIdx.x * blockDim.x + threadIdx.x;
    if (i < BB * FF) out[i] = 0.0f;
    if (i < 2 * BB) (&g_count[0][0])[i] = 0;
}

// ---------------- K0b: pre-split + pre-pack W1 ----------------
__global__ void prep_w_kernel(const float* __restrict__ W1) {
    int i = blockIdx.x * blockDim.x + threadIdx.x;
    if (i >= HH * 64) return;
    int n  = i >> 6;
    int kp = i & 63;
    float w0 = W1[(2 * kp)     * HH + n];
    float w1 = W1[(2 * kp + 1) * HH + n];
    uint32_t hi = bf16x2_pack(w1, w0);
    float h0 = bf16_lo_as_f32(hi);
    float h1 = bf16_hi_as_f32(hi);
    uint32_t lo = bf16x2_pack(w1 - h1, w0 - h0);
    g_wb_hi[i] = hi;
    g_wb_lo[i] = lo;
}

// ---------------- K1: score kernel, per-warp ownership staging ----------------
#define SMEM_WORDS (TILE * XS_STRIDE + 2 * (HH * WB_STRIDE) + 64 + 64)

__global__ __launch_bounds__(256) void score_mma_kernel(
    const float* __restrict__ x1, const float* __restrict__ x2,
    const int* __restrict__ bA, const int* __restrict__ bB,
    const float* __restrict__ b1v, const float* __restrict__ W2)
{
    extern __shared__ float sm[];
    float*    xs  = sm;
    uint32_t* swh = (uint32_t*)(xs + TILE * XS_STRIDE);
    uint32_t* swl = swh + HH * WB_STRIDE;
    float*    b1s = (float*)(swl + HH * WB_STRIDE);
    float*    w2s = b1s + 64;

    const int tid  = threadIdx.x;
    const int wid  = tid >> 5;      // 0..7, each warp owns rows [wid*16, wid*16+16)
    const int lane = tid & 31;
    const int g    = lane >> 2;
    const int tq   = lane & 3;
    const int t    = blockIdx.y;
    const float* x = t ? x2 : x1;
    const int* batch = t ? bB : bA;
    const int n0   = blockIdx.x * TILE;
    const int base = wid * 16;

    // stage packed W (hi+lo): 4096 u32 each — the ONLY CTA-wide barrier
    #pragma unroll
    for (int m = 0; m < 16; ++m) {
        int j = tid + 256 * m;
        int n  = j >> 6;
        int kp = j & 63;
        swh[n * WB_STRIDE + kp] = g_wb_hi[j];
        swl[n * WB_STRIDE + kp] = g_wb_lo[j];
    }
    if (tid < HH) { b1s[tid] = b1v[tid]; w2s[tid] = W2[tid]; }
    __syncthreads();

    // per-warp x staging: this warp loads ONLY its own 16 rows (512B coalesced each)
    #pragma unroll
    for (int i = 0; i < 16; ++i) {
        int r = base + i;
        int node = n0 + r;
        float4 v = make_float4(0.f, 0.f, 0.f, 0.f);
        if (node < NN) v = ((const float4*)x)[node * 32 + lane];
        *(float4*)&xs[r * XS_STRIDE + lane * 4] = v;
    }
    __syncwarp();   // warp-local: no waiting on other warps

    // GEMM: warp computes rows [base, base+16) x 64 hidden (bf16x3 compensated)
    float acc[8][4];
    #pragma unroll
    for (int n = 0; n < 8; ++n)
        #pragma unroll
        for (int c = 0; c < 4; ++c) acc[n][c] = 0.0f;

    #pragma unroll
    for (int kt = 0; kt < 8; ++kt) {
        const int k0  = kt * 16;
        const int kp0 = kt * 8;

        uint32_t bh[8][2], bl[8][2];
        #pragma unroll
        for (int n = 0; n < 8; ++n) {
            int row = (n * 8 + g) * WB_STRIDE + kp0 + tq;
            bh[n][0] = swh[row];
            bh[n][1] = swh[row + 4];
            bl[n][0] = swl[row];
            bl[n][1] = swl[row + 4];
        }

        const int r = base + g;
        float2 q0 = *(const float2*)&xs[r       * XS_STRIDE + k0 + 2 * tq];
        float2 q1 = *(const float2*)&xs[(r + 8) * XS_STRIDE + k0 + 2 * tq];
        float2 q2 = *(const float2*)&xs[r       * XS_STRIDE + k0 + 2 * tq + 8];
        float2 q3 = *(const float2*)&xs[(r + 8) * XS_STRIDE + k0 + 2 * tq + 8];

        uint32_t ahi[4], alo[4];
        split2(q0, ahi[0], alo[0]);
        split2(q1, ahi[1], alo[1]);
        split2(q2, ahi[2], alo[2]);
        split2(q3, ahi[3], alo[3]);

        #pragma unroll
        for (int n = 0; n < 8; ++n) {
            mma_bf16(acc[n], ahi, bh[n]);
            mma_bf16(acc[n], ahi, bl[n]);
            mma_bf16(acc[n], alo, bh[n]);
        }
    }

    // epilogue: tanh + W2 dot, butterfly over the 4 lanes holding each row
    #pragma unroll
    for (int half = 0; half < 2; ++half) {
        float s = 0.0f;
        #pragma unroll
        for (int n = 0; n < 8; ++n) {
            #pragma unroll
            for (int c = 0; c < 2; ++c) {
                int col = n * 8 + 2 * tq + c;
                float h = acc[n][half * 2 + c] + b1s[col];
                s = fmaf(tanh_fast(h), w2s[col], s);
            }
        }
        s += __shfl_xor_sync(0xffffffffu, s, 1);
        s += __shfl_xor_sync(0xffffffffu, s, 2);
        if (tq == 0) {
            int node = n0 + base + half * 8 + g;
            if (node < NN) {
                g_e[t][node] = __expf(s);
                atomicAdd(&g_count[t][batch[node]], 1);
            }
        }
    }
}

// ---------------- K2: exclusive prefix scan over segments ----------------
__global__ void scan_kernel() {
    __shared__ int ss[BB];
    int tid = threadIdx.x;
    for (int t = 0; t < 2; ++t) {
        int v = g_count[t][tid];
        ss[tid] = v;
        __syncthreads();
        for (int d = 1; d < BB; d <<= 1) {
            int add = (tid >= d) ? ss[tid - d] : 0;
            __syncthreads();
            ss[tid] += add;
            __syncthreads();
        }
        int incl = ss[tid];
        g_offset[t][tid] = incl - v;
        g_cursor[t][tid] = incl - v;
        if (tid == BB - 1) g_offset[t][BB] = incl;
        __syncthreads();
    }
}

// ---------------- K3: scatter (x8 ILP, fused 8B pair store) ----------------
__global__ __launch_bounds__(512) void scatter_kernel(
    const int* __restrict__ bA, const int* __restrict__ bB)
{
    int t = blockIdx.y;
    int i0 = (blockIdx.x * 512 + threadIdx.x) * 8;
    if (i0 >= NN) return;                     // NN % 8 == 0, no partial group
    const int* batch = t ? bB : bA;
    int4   bv0 = *(const int4*)&batch[i0];
    int4   bv1 = *(const int4*)&batch[i0 + 4];
    float4 ev0 = *(const float4*)&g_e[t][i0];
    float4 ev1 = *(const float4*)&g_e[t][i0 + 4];
    int p0 = atomicAdd(&g_cursor[t][bv0.x], 1);
    int p1 = atomicAdd(&g_cursor[t][bv0.y], 1);
    int p2 = atomicAdd(&g_cursor[t][bv0.z], 1);
    int p3 = atomicAdd(&g_cursor[t][bv0.w], 1);
    int p4 = atomicAdd(&g_cursor[t][bv1.x], 1);
    int p5 = atomicAdd(&g_cursor[t][bv1.y], 1);
    int p6 = atomicAdd(&g_cursor[t][bv1.z], 1);
    int p7 = atomicAdd(&g_cursor[t][bv1.w], 1);
    g_pair[t][p0] = make_float2(__int_as_float(i0 + 0), ev0.x);
    g_pair[t][p1] = make_float2(__int_as_float(i0 + 1), ev0.y);
    g_pair[t][p2] = make_float2(__int_as_float(i0 + 2), ev0.z);
    g_pair[t][p3] = make_float2(__int_as_float(i0 + 3), ev0.w);
    g_pair[t][p4] = make_float2(__int_as_float(i0 + 4), ev1.x);
    g_pair[t][p5] = make_float2(__int_as_float(i0 + 5), ev1.y);
    g_pair[t][p6] = make_float2(__int_as_float(i0 + 6), ev1.z);
    g_pair[t][p7] = make_float2(__int_as_float(i0 + 7), ev1.w);
}

// ---------------- K4: per-segment weighted pooling (16 warps, 32 rows in flight) ----------------
__global__ __launch_bounds__(512) void pool_kernel(
    const float* __restrict__ x1, const float* __restrict__ x2,
    float* __restrict__ out)
{
    const int t = blockIdx.y;
    const int b = blockIdx.x;
    const float4* x4 = (const float4*)(t ? x2 : x1);
    const int start = g_offset[t][b];
    const int end   = g_offset[t][b + 1];
    const int w = threadIdx.x >> 5;    // warp 0..15 -> row slot
    const int l = threadIdx.x & 31;    // lane -> feature quad

    float4 acc = make_float4(0.f, 0.f, 0.f, 0.f);
    float  es  = 0.0f;

    #pragma unroll 2
    for (int p = start + w; p < end; p += 16) {
        float2 pr = g_pair[t][p];
        int   n = __float_as_int(pr.x);
        float e = pr.y;
        float4 xv = x4[n * 32 + l];
        acc.x = fmaf(e, xv.x, acc.x);
        acc.y = fmaf(e, xv.y, acc.y);
        acc.z = fmaf(e, xv.z, acc.z);
        acc.w = fmaf(e, xv.w, acc.w);
        es += e;
    }

    __shared__ float sacc[16][FF];
    __shared__ float ses[16];
    *(float4*)&sacc[w][4 * l] = acc;
    if (l == 0) ses[w] = es;
    __syncthreads();

    if (threadIdx.x < FF && end > start) {
        int f = threadIdx.x;
        float tot = 0.0f;
        #pragma unroll
        for (int g2 = 0; g2 < 16; ++g2) tot += sacc[g2][f];
        float s = 0.0f;
        #pragma unroll
        for (int g2 = 0; g2 < 16; ++g2) s += ses[g2];
        atomicAdd(&out[b * FF + f], 0.5f * tot / s);
    }
}

// ---------------- launch ----------------
extern "C" void kernel_launch(void* const* d_in, const int* in_sizes, int n_in,
                              void* d_out, int out_size) {
    const float *x1 = 0, *x2 = 0, *W1 = 0, *b1v = 0, *W2 = 0;
    const int *bt1 = 0, *bt2 = 0;
    for (int k = 0; k < n_in; ++k) {
        long s = in_sizes[k];
        if (s == (long)NN * FF) { if (!x1) x1 = (const float*)d_in[k]; else if (!x2) x2 = (const float*)d_in[k]; }
        else if (s == NN)       { if (!bt1) bt1 = (const int*)d_in[k]; else if (!bt2) bt2 = (const int*)d_in[k]; }
        else if (s == FF * HH)  { W1 = (const float*)d_in[k]; }
        else if (s == HH)       { if (!b1v) b1v = (const float*)d_in[k]; else if (!W2) W2 = (const float*)d_in[k]; }
    }
    float* out = (float*)d_out;

    init_kernel<<<(BB * FF + 255) / 256, 256>>>(out);
    prep_w_kernel<<<(HH * 64 + 255) / 256, 256>>>(W1);

    const int smem_bytes = SMEM_WORDS * (int)sizeof(float);
    cudaFuncSetAttribute(score_mma_kernel, cudaFuncAttributeMaxDynamicSharedMemorySize, smem_bytes);
    dim3 g1((NN + TILE - 1) / TILE, 2);
    score_mma_kernel<<<g1, 256, smem_bytes>>>(x1, x2, bt1, bt2, b1v, W2);

    scan_kernel<<<1, BB>>>();

    dim3 g3((NN / 8 + 511) / 512, 2);
    scatter_kernel<<<g3, 512>>>(bt1, bt2);

    dim3 g4(BB, 2);
    pool_kernel<<<g4, 512>>>(x1, x2, out);
}